// round 8
// baseline (speedup 1.0000x reference)
#include <cuda_runtime.h>
#include <math.h>

#define N_NODES 50000
#define N_EDGES 800000
#define E2 (N_EDGES + N_NODES)
#define H 128
#define HV (H / 4)          // float4s per row
#define IN_DIM 64
#define NEG_SLOPE 0.2f

// ---------------- scratch (device globals; 16B-aligned via float4) ----------------
// buffer ids: 0=z, 1=b0, 2=b1, 3=xw, 4=hL
__device__ float4 g_buf[5][(size_t)N_NODES * HV];
__device__ float  g_asv[N_NODES];
__device__ float  g_adv[N_NODES];
__device__ int    g_off[N_NODES + 1];
__device__ int    g_cur[N_NODES];
__device__ int    g_csrc[E2];
__device__ float  g_hbar[H];

__device__ __forceinline__ float* bufF(int s) { return (float*)g_buf[s]; }

// ---------------- edge_index dtype sniff ----------------
// int64 node ids < 2^31 -> every odd 32-bit word is zero. Random int32 ids make
// 8 consecutive zeros astronomically unlikely.
__device__ __forceinline__ bool ei_is64(const int* __restrict__ e32) {
    bool z = true;
    #pragma unroll
    for (int i = 0; i < 8; i++) z = z && (e32[2 * i + 1] == 0);
    return z;
}
__device__ __forceinline__ int ei_at(const int* __restrict__ e32, int elem, bool is64) {
    return is64 ? e32[2 * elem] : e32[elem];
}

// ---------------- small utils ----------------
__global__ void zero_i_kernel(int n) {
    int i = blockIdx.x * blockDim.x + threadIdx.x;
    if (i < n) g_cur[i] = 0;
}
__global__ void zero_hbar_kernel() {
    int i = threadIdx.x;
    if (i < H) g_hbar[i] = 0.f;
}

// ---------------- CSR build ----------------
__global__ void hist_kernel(const int* __restrict__ e32) {
    int e = blockIdx.x * blockDim.x + threadIdx.x;
    if (e >= E2) return;
    bool is64 = ei_is64(e32);
    int dst = (e < N_EDGES) ? ei_at(e32, N_EDGES + e, is64) : (e - N_EDGES);
    if ((unsigned)dst < (unsigned)N_NODES) atomicAdd(&g_cur[dst], 1);
}

// single-block exclusive scan of g_cur (degrees) -> g_off, and g_cur := offsets
__global__ void scan_kernel() {
    __shared__ int wsum[32];
    __shared__ int carry_s;
    int t = threadIdx.x, lane = t & 31, w = t >> 5;
    if (t == 0) carry_s = 0;
    __syncthreads();
    for (int base = 0; base < N_NODES; base += 1024) {
        int idx = base + t;
        int v = (idx < N_NODES) ? g_cur[idx] : 0;
        int x = v;
        #pragma unroll
        for (int o = 1; o < 32; o <<= 1) {
            int y = __shfl_up_sync(0xffffffffu, x, o);
            if (lane >= o) x += y;
        }
        if (lane == 31) wsum[w] = x;
        __syncthreads();
        if (w == 0) {
            int y = wsum[lane];
            int z = y;
            #pragma unroll
            for (int o = 1; o < 32; o <<= 1) {
                int q = __shfl_up_sync(0xffffffffu, z, o);
                if (lane >= o) z += q;
            }
            wsum[lane] = z - y;  // exclusive warp offsets
        }
        __syncthreads();
        int incl = x + wsum[w];
        int excl = incl - v;
        int c = carry_s;
        if (idx < N_NODES) {
            g_off[idx] = c + excl;
            g_cur[idx] = c + excl;
        }
        __syncthreads();
        if (t == 1023) carry_s = c + incl;
        __syncthreads();
    }
    if (t == 0) g_off[N_NODES] = carry_s;
}

__global__ void scatter_kernel(const int* __restrict__ e32) {
    int e = blockIdx.x * blockDim.x + threadIdx.x;
    if (e >= E2) return;
    bool is64 = ei_is64(e32);
    int src, dst;
    if (e < N_EDGES) {
        src = ei_at(e32, e, is64);
        dst = ei_at(e32, N_EDGES + e, is64);
    } else {
        src = e - N_EDGES; dst = src;
    }
    if ((unsigned)dst >= (unsigned)N_NODES) return;            // consistent with hist
    if ((unsigned)src >= (unsigned)N_NODES) src = 0;           // defensive clamp
    int pos = atomicAdd(&g_cur[dst], 1);
    g_csrc[pos] = src;
}

// ---------------- GEMM: C[n,128] = concat(A0[:,:K0], A1[:,:K-K0]) @ W[128,K]^T (+bias)(+relu) ----------------
#define TS 128
#define KC 16
#define SP 132  // padded smem stride (16B-aligned rows)

__global__ __launch_bounds__(256) void gemm128_kernel(
    const float* A0e, const float* A1e, int a0s, int a1s,
    int K0, int K, const float* __restrict__ W,
    const float* __restrict__ bias, int cs,
    int n, int doRelu)
{
    const float* __restrict__ A0 = A0e ? A0e : bufF(a0s);
    const float* __restrict__ A1 = A1e ? A1e : bufF(a1s);
    float* __restrict__ C = bufF(cs);

    __shared__ __align__(16) float As[KC * SP];
    __shared__ __align__(16) float Ws[KC * SP];
    int row0 = blockIdx.x * TS;
    int t = threadIdx.x;
    int tx = t & 15, ty = t >> 4;
    float acc[8][8];
    #pragma unroll
    for (int i = 0; i < 8; i++)
        #pragma unroll
        for (int j = 0; j < 8; j++) acc[i][j] = 0.f;

    int K1 = K - K0;

    for (int k0 = 0; k0 < K; k0 += KC) {
        #pragma unroll
        for (int i = 0; i < 2; i++) {
            int idx = i * 256 + t;          // 0..511
            int r = idx >> 2;               // 0..127
            int kq = (idx & 3) * 4;         // 0,4,8,12
            int k = k0 + kq;
            float4 v = make_float4(0.f, 0.f, 0.f, 0.f);
            int gr = row0 + r;
            if (gr < n) {
                if (k < K0) v = *(const float4*)(A0 + (size_t)gr * K0 + k);
                else        v = *(const float4*)(A1 + (size_t)gr * K1 + (k - K0));
            }
            As[(kq + 0) * SP + r] = v.x;
            As[(kq + 1) * SP + r] = v.y;
            As[(kq + 2) * SP + r] = v.z;
            As[(kq + 3) * SP + r] = v.w;
            float4 wv = *(const float4*)(W + (size_t)r * K + k);
            Ws[(kq + 0) * SP + r] = wv.x;
            Ws[(kq + 1) * SP + r] = wv.y;
            Ws[(kq + 2) * SP + r] = wv.z;
            Ws[(kq + 3) * SP + r] = wv.w;
        }
        __syncthreads();
        #pragma unroll
        for (int kk = 0; kk < KC; kk++) {
            float a[8], b[8];
            *(float4*)&a[0] = *(const float4*)&As[kk * SP + ty * 4];
            *(float4*)&a[4] = *(const float4*)&As[kk * SP + 64 + ty * 4];
            *(float4*)&b[0] = *(const float4*)&Ws[kk * SP + tx * 4];
            *(float4*)&b[4] = *(const float4*)&Ws[kk * SP + 64 + tx * 4];
            #pragma unroll
            for (int i = 0; i < 8; i++)
                #pragma unroll
                for (int j = 0; j < 8; j++)
                    acc[i][j] += a[i] * b[j];
        }
        __syncthreads();
    }

    #pragma unroll
    for (int i = 0; i < 8; i++) {
        int r = (i < 4) ? (ty * 4 + i) : (64 + ty * 4 + i - 4);
        int gr = row0 + r;
        if (gr >= n) continue;
        float4 o0, o1;
        o0.x = acc[i][0]; o0.y = acc[i][1]; o0.z = acc[i][2]; o0.w = acc[i][3];
        o1.x = acc[i][4]; o1.y = acc[i][5]; o1.z = acc[i][6]; o1.w = acc[i][7];
        int c0 = tx * 4, c1 = 64 + tx * 4;
        if (bias) {
            float4 b0 = *(const float4*)(bias + c0);
            float4 b1 = *(const float4*)(bias + c1);
            o0.x += b0.x; o0.y += b0.y; o0.z += b0.z; o0.w += b0.w;
            o1.x += b1.x; o1.y += b1.y; o1.z += b1.z; o1.w += b1.w;
        }
        if (doRelu) {
            o0.x = fmaxf(o0.x, 0.f); o0.y = fmaxf(o0.y, 0.f);
            o0.z = fmaxf(o0.z, 0.f); o0.w = fmaxf(o0.w, 0.f);
            o1.x = fmaxf(o1.x, 0.f); o1.y = fmaxf(o1.y, 0.f);
            o1.z = fmaxf(o1.z, 0.f); o1.w = fmaxf(o1.w, 0.f);
        }
        *(float4*)(C + (size_t)gr * H + c0) = o0;
        *(float4*)(C + (size_t)gr * H + c1) = o1;
    }
}

// ---------------- per-node attention scalars: asv = xw . a_s, adv = xw . a_d ----------------
__global__ void attvec_kernel(const float* __restrict__ a_s,
                              const float* __restrict__ a_d)
{
    int wid = (blockIdx.x * blockDim.x + threadIdx.x) >> 5;
    int lane = threadIdx.x & 31;
    if (wid >= N_NODES) return;
    float4 x = g_buf[3][(size_t)wid * HV + lane];
    float4 a = *(const float4*)(a_s + lane * 4);
    float4 b = *(const float4*)(a_d + lane * 4);
    float s = x.x * a.x + x.y * a.y + x.z * a.z + x.w * a.w;
    float d = x.x * b.x + x.y * b.y + x.z * b.z + x.w * b.w;
    #pragma unroll
    for (int o = 16; o; o >>= 1) {
        s += __shfl_xor_sync(0xffffffffu, s, o);
        d += __shfl_xor_sync(0xffffffffu, d, o);
    }
    if (lane == 0) { g_asv[wid] = s; g_adv[wid] = d; }
}

// ---------------- GAT aggregation (softmax over incoming edges, warp per node) ----------------
__global__ void gat_aggr_kernel(const float* __restrict__ bias, int outSel, int doRelu)
{
    float4* __restrict__ outp = g_buf[outSel];
    const float4* __restrict__ xw = g_buf[3];
    int wid = (blockIdx.x * blockDim.x + threadIdx.x) >> 5;
    int lane = threadIdx.x & 31;
    if (wid >= N_NODES) return;
    int s = g_off[wid], e_end = g_off[wid + 1];
    float advv = g_adv[wid];

    float m = -3.4e38f;
    for (int e = s + lane; e < e_end; e += 32) {
        float v = g_asv[g_csrc[e]] + advv;
        v = (v > 0.f) ? v : NEG_SLOPE * v;
        m = fmaxf(m, v);
    }
    #pragma unroll
    for (int o = 16; o; o >>= 1) m = fmaxf(m, __shfl_xor_sync(0xffffffffu, m, o));

    float den = 0.f;
    for (int e = s + lane; e < e_end; e += 32) {
        float v = g_asv[g_csrc[e]] + advv;
        v = (v > 0.f) ? v : NEG_SLOPE * v;
        den += __expf(v - m);
    }
    #pragma unroll
    for (int o = 16; o; o >>= 1) den += __shfl_xor_sync(0xffffffffu, den, o);
    float inv = 1.f / den;

    float4 acc = make_float4(0.f, 0.f, 0.f, 0.f);
    for (int e = s; e < e_end; e++) {
        int src = g_csrc[e];
        float v = g_asv[src] + advv;
        v = (v > 0.f) ? v : NEG_SLOPE * v;
        float w = __expf(v - m) * inv;
        float4 xv = xw[(size_t)src * HV + lane];
        acc.x += w * xv.x; acc.y += w * xv.y; acc.z += w * xv.z; acc.w += w * xv.w;
    }
    float4 b = *(const float4*)(bias + lane * 4);
    acc.x += b.x; acc.y += b.y; acc.z += b.z; acc.w += b.w;
    if (doRelu) {
        acc.x = fmaxf(acc.x, 0.f); acc.y = fmaxf(acc.y, 0.f);
        acc.z = fmaxf(acc.z, 0.f); acc.w = fmaxf(acc.w, 0.f);
    }
    outp[(size_t)wid * HV + lane] = acc;
}

// ---------------- decoder head: y = sigmoid(buf3 . Wh + bh), warp per node ----------------
__global__ void head_y_kernel(const float* __restrict__ Wh,
                              const float* __restrict__ bh,
                              float* __restrict__ y)
{
    int wid = (blockIdx.x * blockDim.x + threadIdx.x) >> 5;
    int lane = threadIdx.x & 31;
    if (wid >= N_NODES) return;
    float4 x = g_buf[3][(size_t)wid * HV + lane];
    float4 w = *(const float4*)(Wh + lane * 4);
    float s = x.x * w.x + x.y * w.y + x.z * w.z + x.w * w.w;
    #pragma unroll
    for (int o = 16; o; o >>= 1) s += __shfl_xor_sync(0xffffffffu, s, o);
    if (lane == 0) y[wid] = 1.f / (1.f + __expf(-(s + bh[0])));
}

// ---------------- mean over nodes of hL -> g_hbar ----------------
__global__ void hbar_acc_kernel() {
    const float* hL = (const float*)g_buf[4];
    int c = threadIdx.x;   // 128
    int start = blockIdx.x * 256;
    float s = 0.f;
    for (int i = 0; i < 256; i++) {
        int node = start + i;
        if (node < N_NODES) s += hL[(size_t)node * H + c];
    }
    atomicAdd(&g_hbar[c], s);
}

__global__ void term_kernel(const float* __restrict__ Wt,
                            const float* __restrict__ bt,
                            float* __restrict__ tout)
{
    __shared__ float sm[H];
    int c = threadIdx.x;
    sm[c] = g_hbar[c] * (1.f / (float)N_NODES) * Wt[c];
    __syncthreads();
    for (int o = 64; o; o >>= 1) {
        if (c < o) sm[c] += sm[c + o];
        __syncthreads();
    }
    if (c == 0) tout[0] = 1.f / (1.f + __expf(-(sm[0] + bt[0])));
}

// ---------------- copy hL into (possibly unaligned) output slot ----------------
__global__ void copy_hl_kernel(float* __restrict__ dst) {
    const float* hL = (const float*)g_buf[4];
    size_t i = (size_t)blockIdx.x * blockDim.x + threadIdx.x;
    size_t total = (size_t)N_NODES * H;
    for (; i < total; i += (size_t)gridDim.x * blockDim.x) dst[i] = hL[i];
}

// ---------------- launch ----------------
extern "C" void kernel_launch(void* const* d_in, const int* in_sizes, int n_in,
                              void* d_out, int out_size)
{
    const float* x       = (const float*)d_in[0];
    const float* h       = (const float*)d_in[1];
    const int*   ei32    = (const int*)d_in[2];     // int32 OR int64 (device-sniffed)
    const float* W_enc   = (const float*)d_in[3];
    const float* b_enc   = (const float*)d_in[4];
    const float* Wg      = (const float*)d_in[5];
    const float* att_src = (const float*)d_in[6];
    const float* att_dst = (const float*)d_in[7];
    const float* bg      = (const float*)d_in[8];
    const float* Wd      = (const float*)d_in[9];
    const float* bd      = (const float*)d_in[10];
    const float* Wd1     = (const float*)d_in[11];
    const float* bd1     = (const float*)d_in[12];
    const float* Wh      = (const float*)d_in[13];
    const float* bh      = (const float*)d_in[14];
    const float* Wt      = (const float*)d_in[15];
    const float* bt      = (const float*)d_in[16];
    float*       out     = (float*)d_out;

    const int TPB = 256;
    int grid_nodes_w = (N_NODES * 32 + TPB - 1) / TPB;   // warp-per-node kernels
    int grid_edges   = (E2 + TPB - 1) / TPB;
    int grid_gemm    = (N_NODES + TS - 1) / TS;
    const float* NUL = (const float*)0;

    // ---- CSR build ----
    zero_i_kernel<<<(N_NODES + TPB - 1) / TPB, TPB>>>(N_NODES);
    hist_kernel<<<grid_edges, TPB>>>(ei32);
    scan_kernel<<<1, 1024>>>();
    scatter_kernel<<<grid_edges, TPB>>>(ei32);

    // ---- encoder: z(=buf0) = [x|h] @ W_enc^T + b_enc ----
    gemm128_kernel<<<grid_gemm, 256>>>(x, h, 0, 0, IN_DIM, IN_DIM + H, W_enc, b_enc, 0, N_NODES, 0);

    // ---- GAT processor: 3 relu convs + final conv (layer-2 params, no relu) ----
    int inSel[4]  = { 0, 1, 2, 1 };
    int outSel[4] = { 1, 2, 1, 4 };
    int layer_idx[4] = { 0, 1, 2, 2 };
    for (int li = 0; li < 4; li++) {
        int i = layer_idx[li];
        const float* Wi = Wg + (size_t)i * H * H;
        // xw(=buf3) = cur @ Wi^T
        gemm128_kernel<<<grid_gemm, 256>>>(NUL, NUL, inSel[li], inSel[li], H, H, Wi, NUL, 3, N_NODES, 0);
        attvec_kernel<<<grid_nodes_w, TPB>>>(att_src + (size_t)i * H, att_dst + (size_t)i * H);
        gat_aggr_kernel<<<grid_nodes_w, TPB>>>(bg + (size_t)i * H, outSel[li], (li < 3) ? 1 : 0);
    }

    // ---- decoder: d1(=buf2) = relu([hL|z] @ Wd^T + bd); d2(=buf3) = relu(d1 @ Wd1^T + bd1) ----
    gemm128_kernel<<<grid_gemm, 256>>>(NUL, NUL, 4, 0, H, 2 * H, Wd, bd, 2, N_NODES, 1);
    gemm128_kernel<<<grid_gemm, 256>>>(NUL, NUL, 2, 2, H, H, Wd1, bd1, 3, N_NODES, 1);
    head_y_kernel<<<grid_nodes_w, TPB>>>(Wh, bh, out);                 // y -> out[0..N)

    // ---- termination scalar ----
    zero_hbar_kernel<<<1, 128>>>();
    hbar_acc_kernel<<<(N_NODES + 255) / 256, 128>>>();
    term_kernel<<<1, 128>>>(Wt, bt, out + N_NODES);                    // t -> out[N]

    // ---- hL -> out[N+1 ...] ----
    copy_hl_kernel<<<1024, 256>>>(out + N_NODES + 1);
}

// round 12
// speedup vs baseline: 1.3031x; 1.3031x over previous
#include <cuda_runtime.h>
#include <cuda_bf16.h>
#include <cstdint>
#include <math.h>

#define N_NODES 50000
#define N_EDGES 800000
#define E2 (N_EDGES + N_NODES)
#define H 128
#define HV (H / 4)          // float4s per row
#define IN_DIM 64
#define NEG_SLOPE 0.2f

// ---------------- scratch (device globals; 16B-aligned via float4) ----------------
// buffer ids: 0=z, 1=b0, 2=b1, 3=xw, 4=hL
__device__ float4 g_buf[5][(size_t)N_NODES * HV];
__device__ float  g_asv[N_NODES];
__device__ float  g_adv[N_NODES];
__device__ int    g_off[N_NODES + 1];
__device__ int    g_cur[N_NODES];
__device__ int    g_csrc[E2];
__device__ float  g_hbar[H];

__device__ __forceinline__ float* bufF(int s) { return (float*)g_buf[s]; }

// ---------------- edge_index dtype sniff ----------------
__device__ __forceinline__ bool ei_is64(const int* __restrict__ e32) {
    bool z = true;
    #pragma unroll
    for (int i = 0; i < 8; i++) z = z && (e32[2 * i + 1] == 0);
    return z;
}
__device__ __forceinline__ int ei_at(const int* __restrict__ e32, int elem, bool is64) {
    return is64 ? e32[2 * elem] : e32[elem];
}

// ---------------- small utils ----------------
__global__ void zero_i_kernel(int n) {
    int i = blockIdx.x * blockDim.x + threadIdx.x;
    if (i < n) g_cur[i] = 0;
}
__global__ void zero_hbar_kernel() {
    int i = threadIdx.x;
    if (i < H) g_hbar[i] = 0.f;
}

// ---------------- CSR build ----------------
__global__ void hist_kernel(const int* __restrict__ e32) {
    int e = blockIdx.x * blockDim.x + threadIdx.x;
    if (e >= E2) return;
    bool is64 = ei_is64(e32);
    int dst = (e < N_EDGES) ? ei_at(e32, N_EDGES + e, is64) : (e - N_EDGES);
    if ((unsigned)dst < (unsigned)N_NODES) atomicAdd(&g_cur[dst], 1);
}

__global__ void scan_kernel() {
    __shared__ int wsum[32];
    __shared__ int carry_s;
    int t = threadIdx.x, lane = t & 31, w = t >> 5;
    if (t == 0) carry_s = 0;
    __syncthreads();
    for (int base = 0; base < N_NODES; base += 1024) {
        int idx = base + t;
        int v = (idx < N_NODES) ? g_cur[idx] : 0;
        int x = v;
        #pragma unroll
        for (int o = 1; o < 32; o <<= 1) {
            int y = __shfl_up_sync(0xffffffffu, x, o);
            if (lane >= o) x += y;
        }
        if (lane == 31) wsum[w] = x;
        __syncthreads();
        if (w == 0) {
            int y = wsum[lane];
            int z = y;
            #pragma unroll
            for (int o = 1; o < 32; o <<= 1) {
                int q = __shfl_up_sync(0xffffffffu, z, o);
                if (lane >= o) z += q;
            }
            wsum[lane] = z - y;
        }
        __syncthreads();
        int incl = x + wsum[w];
        int excl = incl - v;
        int c = carry_s;
        if (idx < N_NODES) {
            g_off[idx] = c + excl;
            g_cur[idx] = c + excl;
        }
        __syncthreads();
        if (t == 1023) carry_s = c + incl;
        __syncthreads();
    }
    if (t == 0) g_off[N_NODES] = carry_s;
}

__global__ void scatter_kernel(const int* __restrict__ e32) {
    int e = blockIdx.x * blockDim.x + threadIdx.x;
    if (e >= E2) return;
    bool is64 = ei_is64(e32);
    int src, dst;
    if (e < N_EDGES) {
        src = ei_at(e32, e, is64);
        dst = ei_at(e32, N_EDGES + e, is64);
    } else {
        src = e - N_EDGES; dst = src;
    }
    if ((unsigned)dst >= (unsigned)N_NODES) return;
    if ((unsigned)src >= (unsigned)N_NODES) src = 0;
    int pos = atomicAdd(&g_cur[dst], 1);
    g_csrc[pos] = src;
}

// ---------------- tensor-core GEMM (bf16x3 split, mma.sync m16n8k16) ----------------
// C[n,128] = concat(A0[:,:K0], A1[:,:K-K0]) @ W[128,K]^T (+bias)(+relu)
#define TS 128
#define SKP 40   // bf16 smem row stride (80B: conflict-free ldmatrix phases)

__device__ __forceinline__ void ldsm4(uint32_t* r, uint32_t addr) {
    asm volatile("ldmatrix.sync.aligned.m8n8.x4.shared.b16 {%0,%1,%2,%3}, [%4];"
                 : "=r"(r[0]), "=r"(r[1]), "=r"(r[2]), "=r"(r[3]) : "r"(addr));
}
__device__ __forceinline__ void ldsm2(uint32_t* r, uint32_t addr) {
    asm volatile("ldmatrix.sync.aligned.m8n8.x2.shared.b16 {%0,%1}, [%2];"
                 : "=r"(r[0]), "=r"(r[1]) : "r"(addr));
}
__device__ __forceinline__ void mma16816(float* d, const uint32_t* a, const uint32_t* b) {
    asm volatile("mma.sync.aligned.m16n8k16.row.col.f32.bf16.bf16.f32 "
                 "{%0,%1,%2,%3}, {%4,%5,%6,%7}, {%8,%9}, {%0,%1,%2,%3};"
                 : "+f"(d[0]), "+f"(d[1]), "+f"(d[2]), "+f"(d[3])
                 : "r"(a[0]), "r"(a[1]), "r"(a[2]), "r"(a[3]), "r"(b[0]), "r"(b[1]));
}
__device__ __forceinline__ void split_pair(float x, float y,
                                           __nv_bfloat162* hi, __nv_bfloat162* lo) {
    __nv_bfloat16 hx = __float2bfloat16(x), hy = __float2bfloat16(y);
    __nv_bfloat16 lx = __float2bfloat16(x - __bfloat162float(hx));
    __nv_bfloat16 ly = __float2bfloat16(y - __bfloat162float(hy));
    *hi = __halves2bfloat162(hx, hy);
    *lo = __halves2bfloat162(lx, ly);
}

__global__ __launch_bounds__(256, 2) void gemm_tc_kernel(
    const float* A0e, const float* A1e, int a0s, int a1s,
    int K0, int K, const float* __restrict__ W,
    const float* __restrict__ bias, int cs,
    int n, int doRelu)
{
    const float* __restrict__ A0 = A0e ? A0e : bufF(a0s);
    const float* __restrict__ A1 = A1e ? A1e : bufF(a1s);
    float* __restrict__ C = bufF(cs);

    __shared__ __align__(16) __nv_bfloat16 sAh[128 * SKP];
    __shared__ __align__(16) __nv_bfloat16 sAl[128 * SKP];
    __shared__ __align__(16) __nv_bfloat16 sBh[128 * SKP];
    __shared__ __align__(16) __nv_bfloat16 sBl[128 * SKP];

    int t = threadIdx.x, lane = t & 31, warp = t >> 5;
    int wm = warp & 3;        // 0..3 -> M
    int wn = warp >> 2;       // 0..1 -> N
    int row0 = blockIdx.x * TS;
    int K1 = K - K0;

    float acc[2][8][4];
    #pragma unroll
    for (int mt = 0; mt < 2; mt++)
        #pragma unroll
        for (int nt = 0; nt < 8; nt++)
            #pragma unroll
            for (int q = 0; q < 4; q++) acc[mt][nt][q] = 0.f;

    uint32_t baseAh = (uint32_t)__cvta_generic_to_shared(sAh);
    uint32_t baseAl = (uint32_t)__cvta_generic_to_shared(sAl);
    uint32_t baseBh = (uint32_t)__cvta_generic_to_shared(sBh);
    uint32_t baseBl = (uint32_t)__cvta_generic_to_shared(sBl);

    int aRow = lane & 15, aK = (lane >> 4) << 3;   // ldmatrix x4 lane mapping
    int bN = lane & 7,  bK = lane & 8;             // ldmatrix x2: lanes 0-7 -> k+0, 8-15 -> k+8

    for (int k0 = 0; k0 < K; k0 += 32) {
        // ---- stage + split tiles: A[128 x 32], W[128 x 32] ----
        #pragma unroll
        for (int i = 0; i < 4; i++) {
            int id = i * 256 + t;          // 0..1023
            int r  = id >> 3;              // 0..127
            int c4 = (id & 7) * 4;         // 0..28
            int k  = k0 + c4;
            // A (rows may be OOB)
            float4 v = make_float4(0.f, 0.f, 0.f, 0.f);
            int gr = row0 + r;
            if (gr < n) {
                if (k < K0) v = *(const float4*)(A0 + (size_t)gr * K0 + k);
                else        v = *(const float4*)(A1 + (size_t)gr * K1 + (k - K0));
            }
            __nv_bfloat162 h0, l0, h1, l1;
            split_pair(v.x, v.y, &h0, &l0);
            split_pair(v.z, v.w, &h1, &l1);
            *(__nv_bfloat162*)&sAh[r * SKP + c4]     = h0;
            *(__nv_bfloat162*)&sAh[r * SKP + c4 + 2] = h1;
            *(__nv_bfloat162*)&sAl[r * SKP + c4]     = l0;
            *(__nv_bfloat162*)&sAl[r * SKP + c4 + 2] = l1;
            // W (always 128 full rows)
            float4 wv = *(const float4*)(W + (size_t)r * K + k);
            split_pair(wv.x, wv.y, &h0, &l0);
            split_pair(wv.z, wv.w, &h1, &l1);
            *(__nv_bfloat162*)&sBh[r * SKP + c4]     = h0;
            *(__nv_bfloat162*)&sBh[r * SKP + c4 + 2] = h1;
            *(__nv_bfloat162*)&sBl[r * SKP + c4]     = l0;
            *(__nv_bfloat162*)&sBl[r * SKP + c4 + 2] = l1;
        }
        __syncthreads();

        // ---- compute: 2 k-sub x 8 n-tiles x 2 m-tiles x 3 split-mmas ----
        #pragma unroll
        for (int ks = 0; ks < 2; ks++) {
            int kk = ks * 16;
            uint32_t ah[2][4], al[2][4];
            #pragma unroll
            for (int mt = 0; mt < 2; mt++) {
                uint32_t off = (uint32_t)((wm * 32 + mt * 16 + aRow) * SKP + kk + aK) * 2u;
                ldsm4(ah[mt], baseAh + off);
                ldsm4(al[mt], baseAl + off);
            }
            #pragma unroll
            for (int nt = 0; nt < 8; nt++) {
                // non-trans: W rows are n; matrix0 = k+0 (lanes 0-7), matrix1 = k+8 (lanes 8-15)
                uint32_t boff = (uint32_t)((wn * 64 + nt * 8 + bN) * SKP + kk + bK) * 2u;
                uint32_t bh2[2], bl2[2];
                ldsm2(bh2, baseBh + boff);
                ldsm2(bl2, baseBl + boff);
                #pragma unroll
                for (int mt = 0; mt < 2; mt++) {
                    mma16816(acc[mt][nt], ah[mt], bh2);   // hi*hi
                    mma16816(acc[mt][nt], ah[mt], bl2);   // hi*lo
                    mma16816(acc[mt][nt], al[mt], bh2);   // lo*hi
                }
            }
        }
        __syncthreads();
    }

    // ---- epilogue ----
    #pragma unroll
    for (int mt = 0; mt < 2; mt++) {
        #pragma unroll
        for (int nt = 0; nt < 8; nt++) {
            int r = row0 + wm * 32 + mt * 16 + (lane >> 2);
            int c = wn * 64 + nt * 8 + (lane & 3) * 2;
            float d0 = acc[mt][nt][0], d1 = acc[mt][nt][1];
            float d2 = acc[mt][nt][2], d3 = acc[mt][nt][3];
            if (bias) {
                float b0 = bias[c], b1 = bias[c + 1];
                d0 += b0; d1 += b1; d2 += b0; d3 += b1;
            }
            if (doRelu) {
                d0 = fmaxf(d0, 0.f); d1 = fmaxf(d1, 0.f);
                d2 = fmaxf(d2, 0.f); d3 = fmaxf(d3, 0.f);
            }
            if (r < n)     { float2 o = make_float2(d0, d1); *(float2*)(C + (size_t)r * H + c) = o; }
            if (r + 8 < n) { float2 o = make_float2(d2, d3); *(float2*)(C + (size_t)(r + 8) * H + c) = o; }
        }
    }
}

// ---------------- per-node attention scalars: asv = xw . a_s, adv = xw . a_d ----------------
__global__ void attvec_kernel(const float* __restrict__ a_s,
                              const float* __restrict__ a_d)
{
    int wid = (blockIdx.x * blockDim.x + threadIdx.x) >> 5;
    int lane = threadIdx.x & 31;
    if (wid >= N_NODES) return;
    float4 x = g_buf[3][(size_t)wid * HV + lane];
    float4 a = *(const float4*)(a_s + lane * 4);
    float4 b = *(const float4*)(a_d + lane * 4);
    float s = x.x * a.x + x.y * a.y + x.z * a.z + x.w * a.w;
    float d = x.x * b.x + x.y * b.y + x.z * b.z + x.w * b.w;
    #pragma unroll
    for (int o = 16; o; o >>= 1) {
        s += __shfl_xor_sync(0xffffffffu, s, o);
        d += __shfl_xor_sync(0xffffffffu, d, o);
    }
    if (lane == 0) { g_asv[wid] = s; g_adv[wid] = d; }
}

// ---------------- GAT aggregation (softmax over incoming edges, warp per node) ----------------
__global__ void gat_aggr_kernel(const float* __restrict__ bias, int outSel, int doRelu)
{
    float4* __restrict__ outp = g_buf[outSel];
    const float4* __restrict__ xw = g_buf[3];
    int wid = (blockIdx.x * blockDim.x + threadIdx.x) >> 5;
    int lane = threadIdx.x & 31;
    if (wid >= N_NODES) return;
    int s = g_off[wid], e_end = g_off[wid + 1];
    float advv = g_adv[wid];

    float m = -3.4e38f;
    for (int e = s + lane; e < e_end; e += 32) {
        float v = g_asv[g_csrc[e]] + advv;
        v = (v > 0.f) ? v : NEG_SLOPE * v;
        m = fmaxf(m, v);
    }
    #pragma unroll
    for (int o = 16; o; o >>= 1) m = fmaxf(m, __shfl_xor_sync(0xffffffffu, m, o));

    float den = 0.f;
    for (int e = s + lane; e < e_end; e += 32) {
        float v = g_asv[g_csrc[e]] + advv;
        v = (v > 0.f) ? v : NEG_SLOPE * v;
        den += __expf(v - m);
    }
    #pragma unroll
    for (int o = 16; o; o >>= 1) den += __shfl_xor_sync(0xffffffffu, den, o);
    float inv = 1.f / den;

    float4 acc = make_float4(0.f, 0.f, 0.f, 0.f);
    for (int e = s; e < e_end; e++) {
        int src = g_csrc[e];
        float v = g_asv[src] + advv;
        v = (v > 0.f) ? v : NEG_SLOPE * v;
        float w = __expf(v - m) * inv;
        float4 xv = xw[(size_t)src * HV + lane];
        acc.x += w * xv.x; acc.y += w * xv.y; acc.z += w * xv.z; acc.w += w * xv.w;
    }
    float4 b = *(const float4*)(bias + lane * 4);
    acc.x += b.x; acc.y += b.y; acc.z += b.z; acc.w += b.w;
    if (doRelu) {
        acc.x = fmaxf(acc.x, 0.f); acc.y = fmaxf(acc.y, 0.f);
        acc.z = fmaxf(acc.z, 0.f); acc.w = fmaxf(acc.w, 0.f);
    }
    outp[(size_t)wid * HV + lane] = acc;
}

// ---------------- decoder head ----------------
__global__ void head_y_kernel(const float* __restrict__ Wh,
                              const float* __restrict__ bh,
                              float* __restrict__ y)
{
    int wid = (blockIdx.x * blockDim.x + threadIdx.x) >> 5;
    int lane = threadIdx.x & 31;
    if (wid >= N_NODES) return;
    float4 x = g_buf[3][(size_t)wid * HV + lane];
    float4 w = *(const float4*)(Wh + lane * 4);
    float s = x.x * w.x + x.y * w.y + x.z * w.z + x.w * w.w;
    #pragma unroll
    for (int o = 16; o; o >>= 1) s += __shfl_xor_sync(0xffffffffu, s, o);
    if (lane == 0) y[wid] = 1.f / (1.f + __expf(-(s + bh[0])));
}

// ---------------- mean over nodes of hL -> g_hbar ----------------
__global__ void hbar_acc_kernel() {
    const float* hL = (const float*)g_buf[4];
    int c = threadIdx.x;
    int start = blockIdx.x * 256;
    float s = 0.f;
    for (int i = 0; i < 256; i++) {
        int node = start + i;
        if (node < N_NODES) s += hL[(size_t)node * H + c];
    }
    atomicAdd(&g_hbar[c], s);
}

__global__ void term_kernel(const float* __restrict__ Wt,
                            const float* __restrict__ bt,
                            float* __restrict__ tout)
{
    __shared__ float sm[H];
    int c = threadIdx.x;
    sm[c] = g_hbar[c] * (1.f / (float)N_NODES) * Wt[c];
    __syncthreads();
    for (int o = 64; o; o >>= 1) {
        if (c < o) sm[c] += sm[c + o];
        __syncthreads();
    }
    if (c == 0) tout[0] = 1.f / (1.f + __expf(-(sm[0] + bt[0])));
}

// ---------------- copy hL into output slot ----------------
__global__ void copy_hl_kernel(float* __restrict__ dst) {
    const float* hL = (const float*)g_buf[4];
    size_t i = (size_t)blockIdx.x * blockDim.x + threadIdx.x;
    size_t total = (size_t)N_NODES * H;
    for (; i < total; i += (size_t)gridDim.x * blockDim.x) dst[i] = hL[i];
}

// ---------------- launch ----------------
extern "C" void kernel_launch(void* const* d_in, const int* in_sizes, int n_in,
                              void* d_out, int out_size)
{
    const float* x       = (const float*)d_in[0];
    const float* h       = (const float*)d_in[1];
    const int*   ei32    = (const int*)d_in[2];
    const float* W_enc   = (const float*)d_in[3];
    const float* b_enc   = (const float*)d_in[4];
    const float* Wg      = (const float*)d_in[5];
    const float* att_src = (const float*)d_in[6];
    const float* att_dst = (const float*)d_in[7];
    const float* bg      = (const float*)d_in[8];
    const float* Wd      = (const float*)d_in[9];
    const float* bd      = (const float*)d_in[10];
    const float* Wd1     = (const float*)d_in[11];
    const float* bd1     = (const float*)d_in[12];
    const float* Wh      = (const float*)d_in[13];
    const float* bh      = (const float*)d_in[14];
    const float* Wt      = (const float*)d_in[15];
    const float* bt      = (const float*)d_in[16];
    float*       out     = (float*)d_out;

    const int TPB = 256;
    int grid_nodes_w = (N_NODES * 32 + TPB - 1) / TPB;
    int grid_edges   = (E2 + TPB - 1) / TPB;
    int grid_gemm    = (N_NODES + TS - 1) / TS;
    const float* NUL = (const float*)0;

    // ---- CSR build ----
    zero_i_kernel<<<(N_NODES + TPB - 1) / TPB, TPB>>>(N_NODES);
    hist_kernel<<<grid_edges, TPB>>>(ei32);
    scan_kernel<<<1, 1024>>>();
    scatter_kernel<<<grid_edges, TPB>>>(ei32);

    // ---- encoder: z(=buf0) = [x|h] @ W_enc^T + b_enc ----
    gemm_tc_kernel<<<grid_gemm, 256>>>(x, h, 0, 0, IN_DIM, IN_DIM + H, W_enc, b_enc, 0, N_NODES, 0);

    // ---- GAT processor ----
    int inSel[4]  = { 0, 1, 2, 1 };
    int outSel[4] = { 1, 2, 1, 4 };
    int layer_idx[4] = { 0, 1, 2, 2 };
    for (int li = 0; li < 4; li++) {
        int i = layer_idx[li];
        const float* Wi = Wg + (size_t)i * H * H;
        gemm_tc_kernel<<<grid_gemm, 256>>>(NUL, NUL, inSel[li], inSel[li], H, H, Wi, NUL, 3, N_NODES, 0);
        attvec_kernel<<<grid_nodes_w, TPB>>>(att_src + (size_t)i * H, att_dst + (size_t)i * H);
        gat_aggr_kernel<<<grid_nodes_w, TPB>>>(bg + (size_t)i * H, outSel[li], (li < 3) ? 1 : 0);
    }

    // ---- decoder ----
    gemm_tc_kernel<<<grid_gemm, 256>>>(NUL, NUL, 4, 0, H, 2 * H, Wd, bd, 2, N_NODES, 1);
    gemm_tc_kernel<<<grid_gemm, 256>>>(NUL, NUL, 2, 2, H, H, Wd1, bd1, 3, N_NODES, 1);
    head_y_kernel<<<grid_nodes_w, TPB>>>(Wh, bh, out);

    // ---- termination scalar ----
    zero_hbar_kernel<<<1, 128>>>();
    hbar_acc_kernel<<<(N_NODES + 255) / 256, 128>>>();
    term_kernel<<<1, 128>>>(Wt, bt, out + N_NODES);

    // ---- hL -> out[N+1 ...] ----
    copy_hl_kernel<<<1024, 256>>>(out + N_NODES + 1);
}